// round 16
// baseline (speedup 1.0000x reference)
#include <cuda_runtime.h>
#include <cuda_fp16.h>
#include <cstdint>

#define NN   1024
#define FF   200
#define MTOT 65536
#define NEG  0.2f

#define BM 64
#define NTILES (MTOT / BM)           // 1024
#define KSTEPS 13
#define BNP 208
#define CHUNK_B 6656                 // 208 n-rows x 32B (16 fp16) per k-chunk
#define WSMEM (KSTEPS * CHUNK_B)     // 86528 bytes, W resident in smem
#define PERSIST_GRID 304             // 2 CTAs/SM x 152 SMs
#define GT 128                       // gemm threads (4 warps)

// attention (direct-output)
#define AT_ROWS 16
#define ESTR    72
#define HSTR    104

// ---------------- scratch ----------------
__device__ float g_as[NN];
__device__ float g_ad[NN];
__device__ __align__(16) __half g_h0f[NN * FF];
__device__ __align__(16) __half g_Wf[KSTEPS * BNP * 16];

__device__ __forceinline__ float leaky(float z) { return z > 0.f ? z : NEG * z; }

__device__ __forceinline__ void cp_async16(uint32_t dst, const void* src) {
    asm volatile("cp.async.cg.shared.global [%0], [%1], 16;" :: "r"(dst), "l"(src));
}
__device__ __forceinline__ void cp_commit() { asm volatile("cp.async.commit_group;"); }

// ---------------- Kernel P: W -> fp16 smem-image layout (coalesced) --------
__global__ void __launch_bounds__(256) prep_W(const float* __restrict__ W) {
    int id = blockIdx.x * 256 + threadIdx.x;
    if (id >= KSTEPS * BNP) return;
    int n = id % BNP;
    int c = id / BNP;
    __half v[16];
#pragma unroll
    for (int kk = 0; kk < 16; kk++) {
        int k = c * 16 + kk;
        float f = (k < FF && n < FF) ? W[k * FF + n] : 0.f;
        v[kk] = __float2half_rn(f);
    }
    uint4 lo, hi;
    {
        __half2* pl = reinterpret_cast<__half2*>(&lo);
        __half2* ph = reinterpret_cast<__half2*>(&hi);
#pragma unroll
        for (int q = 0; q < 4; q++) {
            pl[q] = __halves2half2(v[2 * q],     v[2 * q + 1]);
            ph[q] = __halves2half2(v[8 + 2 * q], v[8 + 2 * q + 1]);
        }
    }
    char* base = (char*)g_Wf + c * CHUNK_B + n * 32;
    int s = (n >> 2) & 1;
    *reinterpret_cast<uint4*>(base + (s ? 16 : 0)) = lo;
    *reinterpret_cast<uint4*>(base + (s ? 0 : 16)) = hi;
}

// ---------------- Kernel A: persistent GEMM, 4 warps, m32/warp -------------
__global__ void __launch_bounds__(GT, 2) gemm_mma(const float* __restrict__ x,
                                                  const float* __restrict__ att_src,
                                                  const float* __restrict__ att_dst,
                                                  const float* __restrict__ bias,
                                                  float* __restrict__ out,
                                                  int tile_base, int tile_count) {
    extern __shared__ __align__(16) char smem[];
    const uint32_t smem_u = (uint32_t)__cvta_generic_to_shared(smem);

    const int tid  = threadIdx.x;
    const int lane = tid & 31;
    const int warp = tid >> 5;                 // 0..3
    const int warp_m = warp >> 1;              // 0..1 -> rows warp_m*32 (2 m-frags)
    const int warp_n = warp & 1;
    const int m_base = warp_m * 32;
    const int n_base = warp_n * 104;

    // ---- one-time resident W load ----
    for (int idx = tid; idx < WSMEM / 16; idx += GT)
        cp_async16(smem_u + idx * 16, (const char*)g_Wf + idx * 16);
    cp_commit();
    asm volatile("cp.async.wait_group 0;" ::: "memory");
    __syncthreads();

    const int lrow = lane & 7;
    const uint32_t swz = ((((lane >> 3) & 1) ^ ((lrow >> 2) & 1)) << 4);
    const uint32_t b_lane2 = (uint32_t)(n_base + lrow) * 32 + swz;
    const uint32_t b_lane4 = (uint32_t)(n_base + (lane >> 4) * 8 + lrow) * 32 + swz;

    const int g   = lane >> 2;
    const int tig = lane & 3;
    const int qa  = lane & 3;                 // float4 slot this lane LOADS
    const int src0 = (lane & ~3) + (qa >> 1); // shuffle sources (same row group)
    const int src2 = src0 + 2;
    const bool hi_half = (qa & 1);

    for (int tl = blockIdx.x; tl < tile_count; tl += gridDim.x) {
        const int row0 = (tile_base + tl) * BM;
        // lane loads: rows m_base + g (+8, +16, +24), col = ks*16 + 4*qa
        const float* xp0 = x + (size_t)(row0 + m_base + g) * FF + 4 * qa;
        const float* xp1 = xp0 + (size_t)8 * FF;
        const float* xp2 = xp0 + (size_t)16 * FF;
        const float* xp3 = xp0 + (size_t)24 * FF;

        float acc[2][13][4];
#pragma unroll
        for (int mt = 0; mt < 2; mt++)
#pragma unroll
            for (int q = 0; q < 13; q++)
#pragma unroll
                for (int u = 0; u < 4; u++) acc[mt][q][u] = 0.f;

        auto loadA4 = [&](int ks, float4* b) {
            if (ks == KSTEPS - 1 && qa >= 2) {     // cols 200..207 invalid
                b[0] = make_float4(0.f, 0.f, 0.f, 0.f);
                b[1] = b[0]; b[2] = b[0]; b[3] = b[0];
            } else {
                b[0] = *reinterpret_cast<const float4*>(xp0 + ks * 16);
                b[1] = *reinterpret_cast<const float4*>(xp1 + ks * 16);
                b[2] = *reinterpret_cast<const float4*>(xp2 + ks * 16);
                b[3] = *reinterpret_cast<const float4*>(xp3 + ks * 16);
            }
        };

        float4 buf[3][4];
        loadA4(0, buf[0]);
        loadA4(1, buf[1]);
        loadA4(2, buf[2]);

#pragma unroll
        for (int ks = 0; ks < KSTEPS; ks++) {
            const int slot = ks % 3;
            uint32_t a[2][4];
#pragma unroll
            for (int mt = 0; mt < 2; mt++) {
                __half2 hl0v = __floats2half2_rn(buf[slot][2*mt].x,   buf[slot][2*mt].y);
                __half2 hh0v = __floats2half2_rn(buf[slot][2*mt].z,   buf[slot][2*mt].w);
                __half2 hl1v = __floats2half2_rn(buf[slot][2*mt+1].x, buf[slot][2*mt+1].y);
                __half2 hh1v = __floats2half2_rn(buf[slot][2*mt+1].z, buf[slot][2*mt+1].w);
                uint32_t l0 = *reinterpret_cast<uint32_t*>(&hl0v);
                uint32_t h0 = *reinterpret_cast<uint32_t*>(&hh0v);
                uint32_t l1 = *reinterpret_cast<uint32_t*>(&hl1v);
                uint32_t h1 = *reinterpret_cast<uint32_t*>(&hh1v);
                uint32_t p0lo = __shfl_sync(0xffffffffu, l0, src0);
                uint32_t p0hi = __shfl_sync(0xffffffffu, h0, src0);
                uint32_t p1lo = __shfl_sync(0xffffffffu, l1, src0);
                uint32_t p1hi = __shfl_sync(0xffffffffu, h1, src0);
                uint32_t q0lo = __shfl_sync(0xffffffffu, l0, src2);
                uint32_t q0hi = __shfl_sync(0xffffffffu, h0, src2);
                uint32_t q1lo = __shfl_sync(0xffffffffu, l1, src2);
                uint32_t q1hi = __shfl_sync(0xffffffffu, h1, src2);
                a[mt][0] = hi_half ? p0hi : p0lo;
                a[mt][1] = hi_half ? p1hi : p1lo;
                a[mt][2] = hi_half ? q0hi : q0lo;
                a[mt][3] = hi_half ? q1hi : q1lo;
            }
            if (ks + 3 < KSTEPS) loadA4(ks + 3, buf[slot]);

            const uint32_t cb2 = smem_u + ks * CHUNK_B + b_lane2;
            const uint32_t cb4 = smem_u + ks * CHUNK_B + b_lane4;
#pragma unroll
            for (int nt = 0; nt < 12; nt += 2) {
                uint32_t b0, b1, b2, b3;
                asm volatile("ldmatrix.sync.aligned.m8n8.x4.shared.b16 {%0,%1,%2,%3}, [%4];"
                             : "=r"(b0), "=r"(b1), "=r"(b2), "=r"(b3) : "r"(cb4 + nt * 256));
#pragma unroll
                for (int mt = 0; mt < 2; mt++) {
                    asm volatile("mma.sync.aligned.m16n8k16.row.col.f32.f16.f16.f32 "
                                 "{%0,%1,%2,%3}, {%4,%5,%6,%7}, {%8,%9}, {%0,%1,%2,%3};"
                                 : "+f"(acc[mt][nt][0]), "+f"(acc[mt][nt][1]), "+f"(acc[mt][nt][2]), "+f"(acc[mt][nt][3])
                                 : "r"(a[mt][0]), "r"(a[mt][1]), "r"(a[mt][2]), "r"(a[mt][3]), "r"(b0), "r"(b1));
                    asm volatile("mma.sync.aligned.m16n8k16.row.col.f32.f16.f16.f32 "
                                 "{%0,%1,%2,%3}, {%4,%5,%6,%7}, {%8,%9}, {%0,%1,%2,%3};"
                                 : "+f"(acc[mt][nt+1][0]), "+f"(acc[mt][nt+1][1]), "+f"(acc[mt][nt+1][2]), "+f"(acc[mt][nt+1][3])
                                 : "r"(a[mt][0]), "r"(a[mt][1]), "r"(a[mt][2]), "r"(a[mt][3]), "r"(b2), "r"(b3));
                }
            }
            {
                uint32_t b0, b1;
                asm volatile("ldmatrix.sync.aligned.m8n8.x2.shared.b16 {%0,%1}, [%2];"
                             : "=r"(b0), "=r"(b1) : "r"(cb2 + 12 * 256));
#pragma unroll
                for (int mt = 0; mt < 2; mt++) {
                    asm volatile("mma.sync.aligned.m16n8k16.row.col.f32.f16.f16.f32 "
                                 "{%0,%1,%2,%3}, {%4,%5,%6,%7}, {%8,%9}, {%0,%1,%2,%3};"
                                 : "+f"(acc[mt][12][0]), "+f"(acc[mt][12][1]), "+f"(acc[mt][12][2]), "+f"(acc[mt][12][3])
                                 : "r"(a[mt][0]), "r"(a[mt][1]), "r"(a[mt][2]), "r"(a[mt][3]), "r"(b0), "r"(b1));
                }
            }
        }

        if (row0 >= NN) {
#pragma unroll
            for (int mt = 0; mt < 2; mt++) {
                const int r0 = row0 + m_base + mt * 16 + g;
                const int r1 = r0 + 8;
#pragma unroll
                for (int nt = 0; nt < 13; nt++) {
                    int col = n_base + nt * 8 + tig * 2;
                    if (col >= FF) continue;
                    float b0 = bias[col], b1 = bias[col + 1];
                    *reinterpret_cast<float2*>(&out[(size_t)r0 * FF + col]) =
                        make_float2(acc[mt][nt][0] + b0, acc[mt][nt][1] + b1);
                    *reinterpret_cast<float2*>(&out[(size_t)r1 * FF + col]) =
                        make_float2(acc[mt][nt][2] + b0, acc[mt][nt][3] + b1);
                }
            }
        } else {
            // h0 tiles (dedicated 16-CTA launch: 1 tile per CTA -> smem reuse OK)
            float sd[2][2], dd[2][2];
#pragma unroll
            for (int mt = 0; mt < 2; mt++)
                sd[mt][0] = sd[mt][1] = dd[mt][0] = dd[mt][1] = 0.f;
#pragma unroll
            for (int mt = 0; mt < 2; mt++) {
                const int r0 = row0 + m_base + mt * 16 + g;
                const int r1 = r0 + 8;
#pragma unroll
                for (int nt = 0; nt < 13; nt++) {
                    int col = n_base + nt * 8 + tig * 2;
                    if (col >= FF) continue;
                    __half2 p0 = __floats2half2_rn(acc[mt][nt][0], acc[mt][nt][1]);
                    __half2 p1 = __floats2half2_rn(acc[mt][nt][2], acc[mt][nt][3]);
                    *reinterpret_cast<uint32_t*>(&g_h0f[r0 * FF + col]) = *reinterpret_cast<uint32_t*>(&p0);
                    *reinterpret_cast<uint32_t*>(&g_h0f[r1 * FF + col]) = *reinterpret_cast<uint32_t*>(&p1);
                    float sa = att_src[col], sb = att_src[col + 1];
                    float da = att_dst[col], db = att_dst[col + 1];
                    sd[mt][0] = fmaf(acc[mt][nt][0], sa, fmaf(acc[mt][nt][1], sb, sd[mt][0]));
                    dd[mt][0] = fmaf(acc[mt][nt][0], da, fmaf(acc[mt][nt][1], db, dd[mt][0]));
                    sd[mt][1] = fmaf(acc[mt][nt][2], sa, fmaf(acc[mt][nt][3], sb, sd[mt][1]));
                    dd[mt][1] = fmaf(acc[mt][nt][2], da, fmaf(acc[mt][nt][3], db, dd[mt][1]));
                }
            }
            __syncthreads();                   // W reads done -> reuse smem
            float* red = reinterpret_cast<float*>(smem);   // [0..63]=s, [64..127]=d
            red[tid] = 0.f;
            __syncthreads();
#pragma unroll
            for (int mt = 0; mt < 2; mt++) {
                int rr = m_base + mt * 16 + g;
                atomicAdd(&red[rr],          sd[mt][0]);
                atomicAdd(&red[64 + rr],     dd[mt][0]);
                atomicAdd(&red[rr + 8],      sd[mt][1]);
                atomicAdd(&red[64 + rr + 8], dd[mt][1]);
            }
            __syncthreads();
            if (tid < 64) {
                g_as[row0 + tid] = red[tid];
                g_ad[row0 + tid] = red[64 + tid];
            }
        }
    }
}

// ---------------- Kernel B: attention, direct output -----------------------
__global__ void __launch_bounds__(128) attn_mma(const float* __restrict__ bias,
                                                float* __restrict__ out) {
    __shared__ __align__(16) __half sH[2][64 * HSTR];
    __shared__ __align__(16) __half sE[AT_ROWS * ESTR];
    __shared__ float sAs[NN];
    __shared__ float sAd[AT_ROWS];
    __shared__ float sDen[AT_ROWS];

    const int tid  = threadIdx.x;
    const int lane = tid & 31;
    const int warp = tid >> 5;
    const int row0 = blockIdx.x * AT_ROWS;
    const int split = blockIdx.y;
    const int colbase = split * 104;
    const int ntiles = split ? 12 : 13;
    const int gcnt   = ntiles;

    const uint32_t sH_u = (uint32_t)__cvta_generic_to_shared(&sH[0][0]);
    const uint32_t sE_u = (uint32_t)__cvta_generic_to_shared(&sE[0]);
    const uint32_t HBUF = 64 * HSTR * 2;

    for (int i = tid; i < NN; i += 128) sAs[i] = g_as[i];
    if (tid < AT_ROWS) sAd[tid] = g_ad[row0 + tid];

    auto issueH = [&](int c, int p) {
        int j0 = c * 64;
        uint32_t dst = sH_u + p * HBUF;
        for (int idx = tid; idx < 64 * gcnt; idx += 128) {
            int j = idx / gcnt, qq = idx % gcnt;
            cp_async16(dst + (j * HSTR + qq * 8) * 2,
                       (const char*)g_h0f + ((size_t)(j0 + j) * FF + colbase + qq * 8) * 2);
        }
        cp_commit();
    };

    float acc[4][4];
#pragma unroll
    for (int t = 0; t < 4; t++)
#pragma unroll
        for (int u = 0; u < 4; u++) acc[t][u] = 0.f;
    float den_acc = 0.f;

    const int my_ntiles = (ntiles - warp + 3) >> 2;

    const int mi   = lane >> 3;
    const int lrow = lane & 7;
    const int l16  = lane & 15;

    issueH(0, 0);

    const int nchunks = NN / 64;    // 16
    for (int c = 0; c < nchunks; c++) {
        const int p = c & 1;
        if (c + 1 < nchunks) issueH(c + 1, p ^ 1);
        if (c + 1 < nchunks) asm volatile("cp.async.wait_group 1;" ::: "memory");
        else                 asm volatile("cp.async.wait_group 0;" ::: "memory");
        __syncthreads();

        const int j0 = c * 64;
#pragma unroll
        for (int t = 0; t < 8; t++) {
            int idx = tid + t * 128;
            int i = idx >> 6, j = idx & 63;
            float e = __expf(leaky(sAd[i] + sAs[j0 + j]));
            sE[i * ESTR + j] = __float2half_rn(e);
        }
        __syncthreads();

        {
            int rr = tid >> 3, q = tid & 7;
            float s = 0.f;
#pragma unroll
            for (int t = 0; t < 4; t++) {
                __half2 vh = *reinterpret_cast<const __half2*>(&sE[rr * ESTR + q * 8 + 2 * t]);
                s += __half2float(vh.x) + __half2float(vh.y);
            }
            s += __shfl_xor_sync(0xffffffffu, s, 1);
            s += __shfl_xor_sync(0xffffffffu, s, 2);
            s += __shfl_xor_sync(0xffffffffu, s, 4);
            den_acc += s;
        }

        const uint32_t h_base = sH_u + p * HBUF;
#pragma unroll
        for (int kf = 0; kf < 4; kf++) {
            uint32_t a_off = ((lrow + (mi & 1) * 8) * ESTR + kf * 16 + (mi >> 1) * 8) * 2;
            uint32_t e0, e1, e2, e3;
            asm volatile("ldmatrix.sync.aligned.m8n8.x4.shared.b16 {%0,%1,%2,%3}, [%4];"
                         : "=r"(e0), "=r"(e1), "=r"(e2), "=r"(e3) : "r"(sE_u + a_off));
            uint32_t rbase = h_base + ((kf * 16 + l16) * HSTR) * 2;
#pragma unroll
            for (int i = 0; i < 4; i++) {
                if (i >= my_ntiles) break;
                int t = warp + 4 * i;
                uint32_t h0, h1;
                asm volatile("ldmatrix.sync.aligned.m8n8.x2.trans.shared.b16 {%0,%1}, [%2];"
                             : "=r"(h0), "=r"(h1) : "r"(rbase + t * 16));
                asm volatile("mma.sync.aligned.m16n8k16.row.col.f32.f16.f16.f32 "
                             "{%0,%1,%2,%3}, {%4,%5,%6,%7}, {%8,%9}, {%0,%1,%2,%3};"
                             : "+f"(acc[i][0]), "+f"(acc[i][1]), "+f"(acc[i][2]), "+f"(acc[i][3])
                             : "r"(e0), "r"(e1), "r"(e2), "r"(e3), "r"(h0), "r"(h1));
            }
        }
        __syncthreads();
    }

    if ((tid & 7) == 0) sDen[tid >> 3] = den_acc;
    __syncthreads();

    const int g   = lane >> 2;
    const int tig = lane & 3;
    const float inv0 = 1.f / sDen[g];
    const float inv1 = 1.f / sDen[g + 8];
#pragma unroll
    for (int i = 0; i < 4; i++) {
        if (i >= my_ntiles) break;
        int t = warp + 4 * i;
        int col = colbase + t * 8 + tig * 2;
        float b0 = bias[col], b1 = bias[col + 1];
        *reinterpret_cast<float2*>(&out[(size_t)(row0 + g) * FF + col]) =
            make_float2(fmaf(acc[i][0], inv0, b0), fmaf(acc[i][1], inv0, b1));
        *reinterpret_cast<float2*>(&out[(size_t)(row0 + g + 8) * FF + col]) =
            make_float2(fmaf(acc[i][2], inv1, b0), fmaf(acc[i][3], inv1, b1));
    }
}

// ---------------------------------------------------------------------------
extern "C" void kernel_launch(void* const* d_in, const int* in_sizes, int n_in,
                              void* d_out, int out_size) {
    const float* x       = (const float*)d_in[0];
    const float* W       = (const float*)d_in[1];
    const float* att_src = (const float*)d_in[2];
    const float* att_dst = (const float*)d_in[3];
    const float* bias    = (const float*)d_in[4];
    float* out = (float*)d_out;

    static cudaStream_t s2 = nullptr;
    static cudaEvent_t ev_h0 = nullptr, ev_attn = nullptr;
    if (s2 == nullptr) {
        cudaStreamCreateWithFlags(&s2, cudaStreamNonBlocking);
        cudaEventCreateWithFlags(&ev_h0, cudaEventDisableTiming);
        cudaEventCreateWithFlags(&ev_attn, cudaEventDisableTiming);
        cudaFuncSetAttribute(gemm_mma, cudaFuncAttributeMaxDynamicSharedMemorySize, WSMEM);
    }

    prep_W<<<(KSTEPS * BNP + 255) / 256, 256>>>(W);
    // h0 tiles (16 CTAs, one tile each), then fork: attn on s2 || persistent rest
    gemm_mma<<<NN / BM, GT, WSMEM>>>(x, att_src, att_dst, bias, out, 0, NN / BM);
    cudaEventRecord(ev_h0, 0);
    cudaStreamWaitEvent(s2, ev_h0, 0);
    attn_mma<<<dim3(NN / AT_ROWS, 2), 128, 0, s2>>>(bias, out);
    gemm_mma<<<PERSIST_GRID, GT, WSMEM>>>(x, att_src, att_dst, bias, out,
                                          NN / BM, NTILES - NN / BM);
    cudaEventRecord(ev_attn, s2);
    cudaStreamWaitEvent(0, ev_attn, 0);
}

// round 17
// speedup vs baseline: 1.3676x; 1.3676x over previous
#include <cuda_runtime.h>
#include <cuda_fp16.h>
#include <cstdint>

#define NN   1024
#define FF   200
#define MTOT 65536
#define NEG  0.2f

#define BM 64
#define NTILES (MTOT / BM)           // 1024
#define KSTEPS 13
#define BNP 208
#define CHUNK_B 6656                 // 208 n-rows x 32B (16 fp16) per k-chunk
#define WSMEM (KSTEPS * CHUNK_B)     // 86528 bytes, W resident in smem
#define PERSIST_GRID 304             // 2 CTAs/SM x 152 SMs

// attention (direct-output, merged splits)
#define AT_ROWS 16
#define AT_THREADS 256
#define ESTR    72
#define HSTR2   216                  // fp16 cols incl pad; 432B rows, conflict-light
#define ATT_HBUF   (64 * HSTR2 * 2)              // 27648 per buffer
#define ATT_OFF_E  (2 * ATT_HBUF)                // 55296
#define ATT_OFF_AS (ATT_OFF_E + AT_ROWS * ESTR * 2)  // 57600
#define ATT_OFF_AD (ATT_OFF_AS + NN * 4)         // 61696
#define ATT_OFF_DEN (ATT_OFF_AD + 64)            // 61760
#define ATT_SMEM   (ATT_OFF_DEN + 64)            // 61824

// ---------------- scratch ----------------
__device__ float g_as[NN];
__device__ float g_ad[NN];
__device__ __align__(16) __half g_h0f[NN * FF];
__device__ __align__(16) __half g_Wf[KSTEPS * BNP * 16];

__device__ __forceinline__ float leaky(float z) { return z > 0.f ? z : NEG * z; }

__device__ __forceinline__ void cp_async16(uint32_t dst, const void* src) {
    asm volatile("cp.async.cg.shared.global [%0], [%1], 16;" :: "r"(dst), "l"(src));
}
__device__ __forceinline__ void cp_commit() { asm volatile("cp.async.commit_group;"); }

// ---------------- Kernel P: W -> fp16 smem-image layout (coalesced) --------
__global__ void __launch_bounds__(256) prep_W(const float* __restrict__ W) {
    int id = blockIdx.x * 256 + threadIdx.x;
    if (id >= KSTEPS * BNP) return;
    int n = id % BNP;
    int c = id / BNP;
    __half v[16];
#pragma unroll
    for (int kk = 0; kk < 16; kk++) {
        int k = c * 16 + kk;
        float f = (k < FF && n < FF) ? W[k * FF + n] : 0.f;
        v[kk] = __float2half_rn(f);
    }
    uint4 lo, hi;
    {
        __half2* pl = reinterpret_cast<__half2*>(&lo);
        __half2* ph = reinterpret_cast<__half2*>(&hi);
#pragma unroll
        for (int q = 0; q < 4; q++) {
            pl[q] = __halves2half2(v[2 * q],     v[2 * q + 1]);
            ph[q] = __halves2half2(v[8 + 2 * q], v[8 + 2 * q + 1]);
        }
    }
    char* base = (char*)g_Wf + c * CHUNK_B + n * 32;
    int s = (n >> 2) & 1;
    *reinterpret_cast<uint4*>(base + (s ? 16 : 0)) = lo;
    *reinterpret_cast<uint4*>(base + (s ? 0 : 16)) = hi;
}

// ---------------- Kernel A: persistent GEMM (round-10 shape) ---------------
__global__ void __launch_bounds__(256, 2) gemm_mma(const float* __restrict__ x,
                                                   const float* __restrict__ att_src,
                                                   const float* __restrict__ att_dst,
                                                   const float* __restrict__ bias,
                                                   float* __restrict__ out,
                                                   int tile_base, int tile_count) {
    extern __shared__ __align__(16) char smem[];
    const uint32_t smem_u = (uint32_t)__cvta_generic_to_shared(smem);

    const int tid  = threadIdx.x;
    const int lane = tid & 31;
    const int warp = tid >> 5;
    const int warp_m = warp >> 1;
    const int warp_n = warp & 1;
    const int m_base = warp_m * 16;
    const int n_base = warp_n * 104;

    for (int idx = tid; idx < WSMEM / 16; idx += 256)
        cp_async16(smem_u + idx * 16, (const char*)g_Wf + idx * 16);
    cp_commit();
    asm volatile("cp.async.wait_group 0;" ::: "memory");
    __syncthreads();

    const int r   = lane >> 2;
    const int c2  = (lane & 3) * 2;
    const int lrow = lane & 7;
    const uint32_t swz = ((((lane >> 3) & 1) ^ ((lrow >> 2) & 1)) << 4);
    const uint32_t b_lane2 = (uint32_t)(n_base + lrow) * 32 + swz;
    const uint32_t b_lane4 = (uint32_t)(n_base + (lane >> 4) * 8 + lrow) * 32 + swz;

    const int g   = lane >> 2;
    const int tig = lane & 3;

    for (int t = blockIdx.x; t < tile_count; t += gridDim.x) {
        const int row0 = (tile_base + t) * BM;
        const float* xr0 = x + (size_t)(row0 + m_base + r) * FF;
        const float* xr1 = xr0 + 8 * FF;

        float acc[13][4];
#pragma unroll
        for (int q = 0; q < 13; q++)
#pragma unroll
            for (int u = 0; u < 4; u++) acc[q][u] = 0.f;

        auto loadA = [&](int ks, float2* b) {
            int col = ks * 16 + c2;
            b[0] = *reinterpret_cast<const float2*>(xr0 + col);
            b[1] = *reinterpret_cast<const float2*>(xr1 + col);
            if (ks < KSTEPS - 1) {
                b[2] = *reinterpret_cast<const float2*>(xr0 + col + 8);
                b[3] = *reinterpret_cast<const float2*>(xr1 + col + 8);
            } else {
                b[2] = make_float2(0.f, 0.f);
                b[3] = make_float2(0.f, 0.f);
            }
        };

        float2 buf[3][4];
        loadA(0, buf[0]);
        loadA(1, buf[1]);
        loadA(2, buf[2]);

#pragma unroll
        for (int ks = 0; ks < KSTEPS; ks++) {
            const int slot = ks % 3;
            uint32_t a[4];
#pragma unroll
            for (int q = 0; q < 4; q++) {
                __half2 h = __floats2half2_rn(buf[slot][q].x, buf[slot][q].y);
                a[q] = *reinterpret_cast<uint32_t*>(&h);
            }
            if (ks + 3 < KSTEPS) loadA(ks + 3, buf[slot]);

            const uint32_t cb2 = smem_u + ks * CHUNK_B + b_lane2;
            const uint32_t cb4 = smem_u + ks * CHUNK_B + b_lane4;
#pragma unroll
            for (int nt = 0; nt < 12; nt += 2) {
                uint32_t b0, b1, b2, b3;
                asm volatile("ldmatrix.sync.aligned.m8n8.x4.shared.b16 {%0,%1,%2,%3}, [%4];"
                             : "=r"(b0), "=r"(b1), "=r"(b2), "=r"(b3) : "r"(cb4 + nt * 256));
                asm volatile("mma.sync.aligned.m16n8k16.row.col.f32.f16.f16.f32 "
                             "{%0,%1,%2,%3}, {%4,%5,%6,%7}, {%8,%9}, {%0,%1,%2,%3};"
                             : "+f"(acc[nt][0]), "+f"(acc[nt][1]), "+f"(acc[nt][2]), "+f"(acc[nt][3])
                             : "r"(a[0]), "r"(a[1]), "r"(a[2]), "r"(a[3]), "r"(b0), "r"(b1));
                asm volatile("mma.sync.aligned.m16n8k16.row.col.f32.f16.f16.f32 "
                             "{%0,%1,%2,%3}, {%4,%5,%6,%7}, {%8,%9}, {%0,%1,%2,%3};"
                             : "+f"(acc[nt+1][0]), "+f"(acc[nt+1][1]), "+f"(acc[nt+1][2]), "+f"(acc[nt+1][3])
                             : "r"(a[0]), "r"(a[1]), "r"(a[2]), "r"(a[3]), "r"(b2), "r"(b3));
            }
            {
                uint32_t b0, b1;
                asm volatile("ldmatrix.sync.aligned.m8n8.x2.shared.b16 {%0,%1}, [%2];"
                             : "=r"(b0), "=r"(b1) : "r"(cb2 + 12 * 256));
                asm volatile("mma.sync.aligned.m16n8k16.row.col.f32.f16.f16.f32 "
                             "{%0,%1,%2,%3}, {%4,%5,%6,%7}, {%8,%9}, {%0,%1,%2,%3};"
                             : "+f"(acc[12][0]), "+f"(acc[12][1]), "+f"(acc[12][2]), "+f"(acc[12][3])
                             : "r"(a[0]), "r"(a[1]), "r"(a[2]), "r"(a[3]), "r"(b0), "r"(b1));
            }
        }

        const int r0 = row0 + m_base + g;
        const int r1 = r0 + 8;

        if (row0 >= NN) {
#pragma unroll
            for (int nt = 0; nt < 13; nt++) {
                int col = n_base + nt * 8 + tig * 2;
                if (col >= FF) continue;
                float b0 = bias[col], b1 = bias[col + 1];
                *reinterpret_cast<float2*>(&out[(size_t)r0 * FF + col]) =
                    make_float2(acc[nt][0] + b0, acc[nt][1] + b1);
                *reinterpret_cast<float2*>(&out[(size_t)r1 * FF + col]) =
                    make_float2(acc[nt][2] + b0, acc[nt][3] + b1);
            }
        } else {
            float s0 = 0.f, d0 = 0.f, s1 = 0.f, d1 = 0.f;
#pragma unroll
            for (int nt = 0; nt < 13; nt++) {
                int col = n_base + nt * 8 + tig * 2;
                if (col >= FF) continue;
                __half2 p0 = __floats2half2_rn(acc[nt][0], acc[nt][1]);
                __half2 p1 = __floats2half2_rn(acc[nt][2], acc[nt][3]);
                *reinterpret_cast<uint32_t*>(&g_h0f[r0 * FF + col]) = *reinterpret_cast<uint32_t*>(&p0);
                *reinterpret_cast<uint32_t*>(&g_h0f[r1 * FF + col]) = *reinterpret_cast<uint32_t*>(&p1);
                float sa = att_src[col], sb = att_src[col + 1];
                float da = att_dst[col], db = att_dst[col + 1];
                s0 = fmaf(acc[nt][0], sa, fmaf(acc[nt][1], sb, s0));
                d0 = fmaf(acc[nt][0], da, fmaf(acc[nt][1], db, d0));
                s1 = fmaf(acc[nt][2], sa, fmaf(acc[nt][3], sb, s1));
                d1 = fmaf(acc[nt][2], da, fmaf(acc[nt][3], db, d1));
            }
            __syncthreads();
            float* red = reinterpret_cast<float*>(smem);
            if (tid < 128) red[tid] = 0.f;
            __syncthreads();
            atomicAdd(&red[(r0 - row0)],      s0);
            atomicAdd(&red[64 + (r0 - row0)], d0);
            atomicAdd(&red[(r1 - row0)],      s1);
            atomicAdd(&red[64 + (r1 - row0)], d1);
            __syncthreads();
            if (tid < 64) {
                g_as[row0 + tid] = red[tid];
                g_ad[row0 + tid] = red[64 + tid];
            }
        }
    }
}

// ---------------- Kernel B: attention, merged splits, direct output --------
// 64 CTAs x 256 threads; each CTA: 16 out-rows x all 200 cols, sweeps K=1024.
__global__ void __launch_bounds__(AT_THREADS) attn_mma(const float* __restrict__ bias,
                                                       float* __restrict__ out) {
    extern __shared__ __align__(16) char smem[];
    const uint32_t smem_u = (uint32_t)__cvta_generic_to_shared(smem);

    const int tid  = threadIdx.x;
    const int lane = tid & 31;
    const int warp = tid >> 5;               // 0..7
    const int row0 = blockIdx.x * AT_ROWS;

    __half* sE  = reinterpret_cast<__half*>(smem + ATT_OFF_E);
    float* sAs  = reinterpret_cast<float*>(smem + ATT_OFF_AS);
    float* sAd  = reinterpret_cast<float*>(smem + ATT_OFF_AD);
    float* sDen = reinterpret_cast<float*>(smem + ATT_OFF_DEN);
    const uint32_t sE_u = smem_u + ATT_OFF_E;

    for (int i = tid; i < NN; i += AT_THREADS) sAs[i] = g_as[i];
    if (tid < AT_ROWS) sAd[tid] = g_ad[row0 + tid];

    auto issueH = [&](int c, int p) {
        int j0 = c * 64;
        uint32_t dst = smem_u + p * ATT_HBUF;
        for (int idx = tid; idx < 64 * 25; idx += AT_THREADS) {
            int j = idx / 25, q = idx % 25;
            cp_async16(dst + j * (HSTR2 * 2) + q * 16,
                       (const char*)g_h0f + ((size_t)(j0 + j) * FF + q * 8) * 2);
        }
        cp_commit();
    };

    float acc[4][4];
#pragma unroll
    for (int t = 0; t < 4; t++)
#pragma unroll
        for (int u = 0; u < 4; u++) acc[t][u] = 0.f;
    float den_acc = 0.f;

    const int my_ntiles = (25 - warp + 7) >> 3;   // tiles t = warp + 8*i (25 valid tiles)

    const int mi   = lane >> 3;
    const int lrow = lane & 7;
    const int l16  = lane & 15;

    issueH(0, 0);

    const int nchunks = NN / 64;    // 16
    for (int c = 0; c < nchunks; c++) {
        const int p = c & 1;
        if (c + 1 < nchunks) issueH(c + 1, p ^ 1);
        if (c + 1 < nchunks) asm volatile("cp.async.wait_group 1;" ::: "memory");
        else                 asm volatile("cp.async.wait_group 0;" ::: "memory");
        __syncthreads();

        // ---- E tile (16 i x 64 j), computed once ----
        const int j0 = c * 64;
#pragma unroll
        for (int t = 0; t < 4; t++) {
            int idx = tid + t * AT_THREADS;
            int i = idx >> 6, j = idx & 63;
            float e = __expf(leaky(sAd[i] + sAs[j0 + j]));
            sE[i * ESTR + j] = __float2half_rn(e);
        }
        __syncthreads();

        // ---- denominator partial row sums (16 lanes per row) ----
        {
            int rr = tid >> 4, q = tid & 15;
            float s = 0.f;
#pragma unroll
            for (int t = 0; t < 2; t++) {
                __half2 vh = *reinterpret_cast<const __half2*>(&sE[rr * ESTR + q * 4 + 2 * t]);
                s += __half2float(vh.x) + __half2float(vh.y);
            }
            s += __shfl_xor_sync(0xffffffffu, s, 1);
            s += __shfl_xor_sync(0xffffffffu, s, 2);
            s += __shfl_xor_sync(0xffffffffu, s, 4);
            s += __shfl_xor_sync(0xffffffffu, s, 8);
            den_acc += s;
        }

        // ---- MMAs: 8 warps split the 25 n-tiles ----
        const uint32_t h_base = smem_u + p * ATT_HBUF;
#pragma unroll
        for (int kf = 0; kf < 4; kf++) {
            uint32_t a_off = ((lrow + (mi & 1) * 8) * ESTR + kf * 16 + (mi >> 1) * 8) * 2;
            uint32_t e0, e1, e2, e3;
            asm volatile("ldmatrix.sync.aligned.m8n8.x4.shared.b16 {%0,%1,%2,%3}, [%4];"
                         : "=r"(e0), "=r"(e1), "=r"(e2), "=r"(e3) : "r"(sE_u + a_off));
            uint32_t rbase = h_base + (kf * 16 + l16) * (HSTR2 * 2);
#pragma unroll
            for (int i = 0; i < 4; i++) {
                if (i >= my_ntiles) break;
                int t = warp + 8 * i;
                uint32_t h0, h1;
                asm volatile("ldmatrix.sync.aligned.m8n8.x2.trans.shared.b16 {%0,%1}, [%2];"
                             : "=r"(h0), "=r"(h1) : "r"(rbase + t * 16));
                asm volatile("mma.sync.aligned.m16n8k16.row.col.f32.f16.f16.f32 "
                             "{%0,%1,%2,%3}, {%4,%5,%6,%7}, {%8,%9}, {%0,%1,%2,%3};"
                             : "+f"(acc[i][0]), "+f"(acc[i][1]), "+f"(acc[i][2]), "+f"(acc[i][3])
                             : "r"(e0), "r"(e1), "r"(e2), "r"(e3), "r"(h0), "r"(h1));
            }
        }
        __syncthreads();
    }

    if ((tid & 15) == 0) sDen[tid >> 4] = den_acc;
    __syncthreads();

    const int g   = lane >> 2;
    const int tig = lane & 3;
    const float inv0 = 1.f / sDen[g];
    const float inv1 = 1.f / sDen[g + 8];
#pragma unroll
    for (int i = 0; i < 4; i++) {
        if (i >= my_ntiles) break;
        int t = warp + 8 * i;
        int col = t * 8 + tig * 2;
        float b0 = bias[col], b1 = bias[col + 1];
        *reinterpret_cast<float2*>(&out[(size_t)(row0 + g) * FF + col]) =
            make_float2(fmaf(acc[i][0], inv0, b0), fmaf(acc[i][1], inv0, b1));
        *reinterpret_cast<float2*>(&out[(size_t)(row0 + g + 8) * FF + col]) =
            make_float2(fmaf(acc[i][2], inv1, b0), fmaf(acc[i][3], inv1, b1));
    }
}

// ---------------------------------------------------------------------------
extern "C" void kernel_launch(void* const* d_in, const int* in_sizes, int n_in,
                              void* d_out, int out_size) {
    const float* x       = (const float*)d_in[0];
    const float* W       = (const float*)d_in[1];
    const float* att_src = (const float*)d_in[2];
    const float* att_dst = (const float*)d_in[3];
    const float* bias    = (const float*)d_in[4];
    float* out = (float*)d_out;

    static cudaStream_t s2 = nullptr;
    static cudaEvent_t ev_h0 = nullptr, ev_attn = nullptr;
    if (s2 == nullptr) {
        cudaStreamCreateWithFlags(&s2, cudaStreamNonBlocking);
        cudaEventCreateWithFlags(&ev_h0, cudaEventDisableTiming);
        cudaEventCreateWithFlags(&ev_attn, cudaEventDisableTiming);
        cudaFuncSetAttribute(gemm_mma, cudaFuncAttributeMaxDynamicSharedMemorySize, WSMEM);
        cudaFuncSetAttribute(attn_mma, cudaFuncAttributeMaxDynamicSharedMemorySize, ATT_SMEM);
    }

    prep_W<<<(KSTEPS * BNP + 255) / 256, 256>>>(W);
    // h0 tiles (16 CTAs, one tile each), then fork: attn on s2 || persistent rest
    gemm_mma<<<NN / BM, 256, WSMEM>>>(x, att_src, att_dst, bias, out, 0, NN / BM);
    cudaEventRecord(ev_h0, 0);
    cudaStreamWaitEvent(s2, ev_h0, 0);
    attn_mma<<<NN / AT_ROWS, AT_THREADS, ATT_SMEM, s2>>>(bias, out);
    gemm_mma<<<PERSIST_GRID, 256, WSMEM>>>(x, att_src, att_dst, bias, out,
                                           NN / BM, NTILES - NN / BM);
    cudaEventRecord(ev_attn, s2);
    cudaStreamWaitEvent(0, ev_attn, 0);
}